// round 13
// baseline (speedup 1.0000x reference)
#include <cuda_runtime.h>
#include <cuda_fp16.h>
#include <cuda_bf16.h>
#include <cstdint>

#define N_NODES 40000
#define N_EDGES 640000
#define D 128
#define BN_EPS 1e-5f
#define KP 136   // padded K stride (bf16) -> conflict-free MMA frags
#define GEMM_GRID 313   // 2 row-tiles of 64 per CTA: tiles bid, bid+313

// ---------------- device scratch (no allocations allowed) ----------------
__device__ __half g_h16[(size_t)N_NODES * D];          // f16 copy of h (messages)
__device__ __nv_bfloat16 g_hnhi[(size_t)N_NODES * D];  // bf16 hi of hneigh
__device__ __nv_bfloat16 g_hnlo[(size_t)N_NODES * D];  // bf16 lo of hneigh
__device__ float  g_y[(size_t)N_NODES * D];            // pre-batchnorm activations
__device__ int    g_cnt[N_NODES];                      // zero-init; re-zeroed by k_final
__device__ int    g_rowstart[N_NODES];
__device__ int    g_fill[N_NODES];
__device__ int    g_csr[N_EDGES];
__device__ int    g_total;
__device__ float  g_colsum[D];
__device__ float  g_colsq[D];
__device__ __align__(16) __nv_bfloat16 g_Bw[2][2][128 * KP];

// ---------------- K1: prep: h->f16, hist, W split, zero stats ------------
__global__ void __launch_bounds__(256) k_prep(const float* __restrict__ h,
                                              const int* __restrict__ dst,
                                              const float* __restrict__ Ws,
                                              const float* __restrict__ Wn) {
    int i = blockIdx.x * 256 + threadIdx.x;
    if (i < N_NODES * (D / 4)) {
        float4 v = ((const float4*)h)[i];
        __half2 m0 = __floats2half2_rn(v.x, v.y);
        __half2 m1 = __floats2half2_rn(v.z, v.w);
        ((uint2*)g_h16)[i] = make_uint2(*(unsigned*)&m0, *(unsigned*)&m1);
    }
    if (i < N_EDGES) atomicAdd(&g_cnt[dst[i]], 1);
    if (i < 2 * D * D) {                       // W^T hi/lo split images
        int chunk = i >> 14;
        int n = (i >> 7) & 127;
        int k = i & 127;
        float w = (chunk == 0 ? Ws : Wn)[k * D + n];
        __nv_bfloat16 hi = __float2bfloat16(w);
        __nv_bfloat16 lo = __float2bfloat16(w - __bfloat162float(hi));
        g_Bw[chunk][0][n * KP + k] = hi;
        g_Bw[chunk][1][n * KP + k] = lo;
    }
    if (i < D) { g_colsum[i] = 0.f; g_colsq[i] = 0.f; }
    if (i == 0) g_total = 0;
}

// ---------------- K2: scan; disjoint block bases via atomic --------------
__global__ void __launch_bounds__(256) k_scan() {
    __shared__ int wsum[8];
    __shared__ int sbase;
    int i = blockIdx.x * 256 + threadIdx.x;
    int lane = threadIdx.x & 31;
    int wd = threadIdx.x >> 5;
    int c = (i < N_NODES) ? g_cnt[i] : 0;
    int v = c;
    #pragma unroll
    for (int off = 1; off < 32; off <<= 1) {
        int t = __shfl_up_sync(0xFFFFFFFF, v, off);
        if (lane >= off) v += t;
    }
    if (lane == 31) wsum[wd] = v;
    __syncthreads();
    if (threadIdx.x < 8) {
        int ws = wsum[threadIdx.x];
        int p = ws;
        #pragma unroll
        for (int off = 1; off < 8; off <<= 1) {
            int t = __shfl_up_sync(0xFF, p, off);
            if ((int)threadIdx.x >= off) p += t;
        }
        wsum[threadIdx.x] = p - ws;
        if (threadIdx.x == 7) sbase = atomicAdd(&g_total, p);
    }
    __syncthreads();
    if (i < N_NODES) {
        int excl = sbase + wsum[wd] + v - c;
        g_rowstart[i] = excl;
        g_fill[i] = excl;
    }
}

// ---------------- K3: fill CSR ----------------
__global__ void __launch_bounds__(256) k_fill(const int* __restrict__ src,
                                              const int* __restrict__ dst) {
    int e = blockIdx.x * blockDim.x + threadIdx.x;
    if (e < N_EDGES) {
        int d = dst[e];
        int pos = atomicAdd(&g_fill[d], 1);
        g_csr[pos] = src[e];
    }
}

// ---------------- K4: warp-per-node gather -> bf16 hi/lo output ----------
__device__ __forceinline__ void add8f(float* a, uint4 u) {
    float2 f;
    f = __half22float2(*(__half2*)&u.x); a[0] += f.x; a[1] += f.y;
    f = __half22float2(*(__half2*)&u.y); a[2] += f.x; a[3] += f.y;
    f = __half22float2(*(__half2*)&u.z); a[4] += f.x; a[5] += f.y;
    f = __half22float2(*(__half2*)&u.w); a[6] += f.x; a[7] += f.y;
}
__global__ void __launch_bounds__(256) k_gather() {
    int w = (blockIdx.x * 256 + threadIdx.x) >> 5;
    int lane = threadIdx.x & 31;
    if (w >= N_NODES) return;
    int rs  = g_rowstart[w];
    int deg = g_cnt[w];
    int hl = lane >> 4;
    int li = lane & 15;
    const uint4* hp = (const uint4*)g_h16;

    float acc[8] = {0.f, 0.f, 0.f, 0.f, 0.f, 0.f, 0.f, 0.f};
    int j = 0;
    for (; j + 4 <= deg; j += 4) {
        int sA = g_csr[rs + j + hl];
        int sB = g_csr[rs + j + 2 + hl];
        uint4 uA = hp[(size_t)sA * 16 + li];
        uint4 uB = hp[(size_t)sB * 16 + li];
        __half2 p0 = __hadd2(*(__half2*)&uA.x, *(__half2*)&uB.x);
        __half2 p1 = __hadd2(*(__half2*)&uA.y, *(__half2*)&uB.y);
        __half2 p2 = __hadd2(*(__half2*)&uA.z, *(__half2*)&uB.z);
        __half2 p3 = __hadd2(*(__half2*)&uA.w, *(__half2*)&uB.w);
        float2 f;
        f = __half22float2(p0); acc[0] += f.x; acc[1] += f.y;
        f = __half22float2(p1); acc[2] += f.x; acc[3] += f.y;
        f = __half22float2(p2); acc[4] += f.x; acc[5] += f.y;
        f = __half22float2(p3); acc[6] += f.x; acc[7] += f.y;
    }
    for (; j + 2 <= deg; j += 2) {
        int sA = g_csr[rs + j + hl];
        add8f(acc, hp[(size_t)sA * 16 + li]);
    }
    if (j < deg && hl == 0) {
        int sA = g_csr[rs + j];
        add8f(acc, hp[(size_t)sA * 16 + li]);
    }
    #pragma unroll
    for (int k = 0; k < 8; k++)
        acc[k] += __shfl_down_sync(0xFFFFFFFF, acc[k], 16);
    if (hl == 0) {
        float inv = 1.0f / fmaxf((float)deg, 1.0f);
        #pragma unroll
        for (int k = 0; k < 8; k++) acc[k] *= inv;
        __nv_bfloat162 h0 = __floats2bfloat162_rn(acc[0], acc[1]);
        __nv_bfloat162 h1 = __floats2bfloat162_rn(acc[2], acc[3]);
        __nv_bfloat162 h2 = __floats2bfloat162_rn(acc[4], acc[5]);
        __nv_bfloat162 h3 = __floats2bfloat162_rn(acc[6], acc[7]);
        float2 f0 = __bfloat1622float2(h0);
        float2 f1 = __bfloat1622float2(h1);
        float2 f2 = __bfloat1622float2(h2);
        float2 f3 = __bfloat1622float2(h3);
        __nv_bfloat162 l0 = __floats2bfloat162_rn(acc[0] - f0.x, acc[1] - f0.y);
        __nv_bfloat162 l1 = __floats2bfloat162_rn(acc[2] - f1.x, acc[3] - f1.y);
        __nv_bfloat162 l2 = __floats2bfloat162_rn(acc[4] - f2.x, acc[5] - f2.y);
        __nv_bfloat162 l3 = __floats2bfloat162_rn(acc[6] - f3.x, acc[7] - f3.y);
        ((uint4*)g_hnhi)[(size_t)w * 16 + li] =
            make_uint4(*(unsigned*)&h0, *(unsigned*)&h1, *(unsigned*)&h2, *(unsigned*)&h3);
        ((uint4*)g_hnlo)[(size_t)w * 16 + li] =
            make_uint4(*(unsigned*)&l0, *(unsigned*)&l1, *(unsigned*)&l2, *(unsigned*)&l3);
    }
}

// ---------------- K5: M=64 HMMA GEMM, 2 tiles/CTA, B reused --------------
#define AT (64 * KP)                       // one A tile (elems)
#define BT (128 * KP)                      // one B tile (elems)
#define SM_TOTAL ((2 * AT + 2 * BT) * 2)   // bytes: 104448

__device__ __forceinline__ void mma_bf16(float* c, uint32_t a0, uint32_t a1,
                                         uint32_t a2, uint32_t a3,
                                         uint32_t b0, uint32_t b1) {
    asm volatile(
        "mma.sync.aligned.m16n8k16.row.col.f32.bf16.bf16.f32 "
        "{%0,%1,%2,%3}, {%4,%5,%6,%7}, {%8,%9}, {%0,%1,%2,%3};"
        : "+f"(c[0]), "+f"(c[1]), "+f"(c[2]), "+f"(c[3])
        : "r"(a0), "r"(a1), "r"(a2), "r"(a3), "r"(b0), "r"(b1));
}

// 3-term split passes (reads SMEM tiles, accumulates 8x4 per warp)
__device__ __forceinline__ void gemm_passes(const __nv_bfloat16* Ahi,
                                            const __nv_bfloat16* Alo,
                                            const __nv_bfloat16* Bhi,
                                            const __nv_bfloat16* Blo,
                                            int rt, int nh, int g, int t,
                                            float acc[8][4]) {
    #pragma unroll
    for (int ks = 0; ks < 8; ks++) {
        const int k0 = ks * 16;
        const __nv_bfloat16* ar0 = Ahi + (rt * 16 + g) * KP + k0 + t * 2;
        const __nv_bfloat16* ar1 = ar0 + 8 * KP;
        uint32_t ah0 = *(const uint32_t*)ar0;
        uint32_t ah2 = *(const uint32_t*)(ar0 + 8);
        uint32_t ah1 = *(const uint32_t*)ar1;
        uint32_t ah3 = *(const uint32_t*)(ar1 + 8);
        const __nv_bfloat16* al0p = Alo + (rt * 16 + g) * KP + k0 + t * 2;
        const __nv_bfloat16* al1p = al0p + 8 * KP;
        uint32_t al0 = *(const uint32_t*)al0p;
        uint32_t al2 = *(const uint32_t*)(al0p + 8);
        uint32_t al1 = *(const uint32_t*)al1p;
        uint32_t al3 = *(const uint32_t*)(al1p + 8);
        #pragma unroll
        for (int nt = 0; nt < 8; nt++) {
            const __nv_bfloat16* br = Bhi + ((nh * 8 + nt) * 8 + g) * KP + k0 + t * 2;
            uint32_t b0 = *(const uint32_t*)br;
            uint32_t b1 = *(const uint32_t*)(br + 8);
            mma_bf16(acc[nt], ah0, ah1, ah2, ah3, b0, b1);
            mma_bf16(acc[nt], al0, al1, al2, al3, b0, b1);
        }
    }
    #pragma unroll
    for (int ks = 0; ks < 8; ks++) {
        const int k0 = ks * 16;
        const __nv_bfloat16* ar0 = Ahi + (rt * 16 + g) * KP + k0 + t * 2;
        const __nv_bfloat16* ar1 = ar0 + 8 * KP;
        uint32_t ah0 = *(const uint32_t*)ar0;
        uint32_t ah2 = *(const uint32_t*)(ar0 + 8);
        uint32_t ah1 = *(const uint32_t*)ar1;
        uint32_t ah3 = *(const uint32_t*)(ar1 + 8);
        #pragma unroll
        for (int nt = 0; nt < 8; nt++) {
            const __nv_bfloat16* br = Blo + ((nh * 8 + nt) * 8 + g) * KP + k0 + t * 2;
            uint32_t b0 = *(const uint32_t*)br;
            uint32_t b1 = *(const uint32_t*)(br + 8);
            mma_bf16(acc[nt], ah0, ah1, ah2, ah3, b0, b1);
        }
    }
}

// stage one A tile: chunk0 = convert from h fp32; chunk1 = copy hn hi/lo
__device__ __forceinline__ void stageA(__nv_bfloat16* Ahi, __nv_bfloat16* Alo,
                                       const float* h, int chunk, int row0,
                                       int tid, bool valid) {
    if (chunk == 0) {
        int arow = tid >> 2;           // 0..63
        int q = tid & 3;               // 32-col quarter
        const float4* sp = (const float4*)(h + (size_t)(row0 + arow) * D + q * 32);
        __nv_bfloat16* ah = Ahi + arow * KP + q * 32;
        __nv_bfloat16* al = Alo + arow * KP + q * 32;
        #pragma unroll
        for (int i = 0; i < 8; i++) {
            float4 v = valid ? sp[i] : make_float4(0.f, 0.f, 0.f, 0.f);
            __nv_bfloat162 h0 = __floats2bfloat162_rn(v.x, v.y);
            __nv_bfloat162 h1 = __floats2bfloat162_rn(v.z, v.w);
            float2 f0 = __bfloat1622float2(h0);
            float2 f1 = __bfloat1622float2(h1);
            __nv_bfloat162 l0 = __floats2bfloat162_rn(v.x - f0.x, v.y - f0.y);
            __nv_bfloat162 l1 = __floats2bfloat162_rn(v.z - f1.x, v.w - f1.y);
            *(uint2*)(ah + i * 4) = make_uint2(*(uint32_t*)&h0, *(uint32_t*)&h1);
            *(uint2*)(al + i * 4) = make_uint2(*(uint32_t*)&l0, *(uint32_t*)&l1);
        }
    } else {
        int abuf = tid >> 7;           // 0=hi, 1=lo
        int aidx = tid & 127;
        int arow = aidx >> 1;
        int ahf = aidx & 1;
        const __nv_bfloat16* gsrc = abuf ? g_hnlo : g_hnhi;
        const uint4* sp = (const uint4*)(gsrc + (size_t)(row0 + arow) * D + ahf * 64);
        uint4* dp = (uint4*)((abuf ? Alo : Ahi) + arow * KP + ahf * 64);
        uint4 z = make_uint4(0, 0, 0, 0);
        #pragma unroll
        for (int i = 0; i < 8; i++) dp[i] = valid ? sp[i] : z;
    }
}

__global__ void __launch_bounds__(256, 2) k_gemm_mma(const float* __restrict__ h,
                                                     const float* __restrict__ bias,
                                                     const float* __restrict__ snorm) {
    extern __shared__ __align__(16) __nv_bfloat16 smem[];
    __nv_bfloat16* Ahi = smem;
    __nv_bfloat16* Alo = smem + AT;
    __nv_bfloat16* Bhi = smem + 2 * AT;
    __nv_bfloat16* Blo = smem + 2 * AT + BT;
    __shared__ float red[D];
    __shared__ float redq[D];

    const int tid = threadIdx.x;
    const int w   = tid >> 5;
    const int lane = tid & 31;
    const int g = lane >> 2;
    const int t = lane & 3;
    const int rt = w & 3;
    const int nh = w >> 2;

    const int row0_0 = blockIdx.x * 64;                   // tile 0
    const int row0_1 = (blockIdx.x + GEMM_GRID) * 64;     // tile 1
    const bool v1 = (row0_1 < N_NODES);

    if (tid < D) { red[tid] = 0.f; redq[tid] = 0.f; }

    float acc[2][8][4];
    #pragma unroll
    for (int ti = 0; ti < 2; ti++)
        #pragma unroll
        for (int nt = 0; nt < 8; nt++)
            #pragma unroll
            for (int c = 0; c < 4; c++) acc[ti][nt][c] = 0.f;

    for (int chunk = 0; chunk < 2; chunk++) {
        __syncthreads();
        // B for this chunk (reused across both tiles)
        {
            const uint4* bsrc = (const uint4*)&g_Bw[chunk][0][0];
            uint4* bdst = (uint4*)Bhi;
            #pragma unroll
            for (int i = 0; i < 17; i++) bdst[tid + i * 256] = bsrc[tid + i * 256];
        }
        stageA(Ahi, Alo, h, chunk, row0_0, tid, true);
        __syncthreads();
        gemm_passes(Ahi, Alo, Bhi, Blo, rt, nh, g, t, acc[0]);
        __syncthreads();
        if (v1) {
            stageA(Ahi, Alo, h, chunk, row0_1, tid, true);
            __syncthreads();
            gemm_passes(Ahi, Alo, Bhi, Blo, rt, nh, g, t, acc[1]);
        }
    }

    // ---- epilogue per tile: bias + relu + snorm -> g_y ; fused stats ----
    #pragma unroll
    for (int ti = 0; ti < 2; ti++) {
        if (ti == 1 && !v1) break;
        int row0 = ti ? row0_1 : row0_0;
        int rowa = row0 + rt * 16 + g;
        int rowb = rowa + 8;
        float sna = snorm[rowa];
        float snb = snorm[rowb];
        #pragma unroll
        for (int nt = 0; nt < 8; nt++) {
            int col = nh * 64 + nt * 8 + t * 2;
            float b0 = bias[col], b1 = bias[col + 1];
            float2 oa, ob;
            oa.x = fmaxf(acc[ti][nt][0] + b0, 0.f) * sna;
            oa.y = fmaxf(acc[ti][nt][1] + b1, 0.f) * sna;
            ob.x = fmaxf(acc[ti][nt][2] + b0, 0.f) * snb;
            ob.y = fmaxf(acc[ti][nt][3] + b1, 0.f) * snb;
            *(float2*)(g_y + (size_t)rowa * D + col) = oa;
            *(float2*)(g_y + (size_t)rowb * D + col) = ob;
            float s0 = oa.x + ob.x, s1 = oa.y + ob.y;
            float q0 = oa.x * oa.x + ob.x * ob.x, q1 = oa.y * oa.y + ob.y * ob.y;
            #pragma unroll
            for (int off = 16; off >= 4; off >>= 1) {
                s0 += __shfl_down_sync(0xFFFFFFFF, s0, off);
                s1 += __shfl_down_sync(0xFFFFFFFF, s1, off);
                q0 += __shfl_down_sync(0xFFFFFFFF, q0, off);
                q1 += __shfl_down_sync(0xFFFFFFFF, q1, off);
            }
            if (g == 0) {
                atomicAdd(&red[col], s0);
                atomicAdd(&red[col + 1], s1);
                atomicAdd(&redq[col], q0);
                atomicAdd(&redq[col + 1], q1);
            }
        }
    }
    __syncthreads();
    if (tid < D) {
        atomicAdd(&g_colsum[tid], red[tid]);
        atomicAdd(&g_colsq[tid], redq[tid]);
    }
}

// ---------------- K6: out = h + y*scale + shift ; re-zero g_cnt ----------
__global__ void __launch_bounds__(256) k_final(const float* __restrict__ h,
                                               const float* __restrict__ gamma,
                                               const float* __restrict__ beta,
                                               float* __restrict__ out) {
    __shared__ float ssc[D], ssh[D];
    if (threadIdx.x < D) {
        int c = threadIdx.x;
        float m  = g_colsum[c] * (1.0f / N_NODES);
        float va = g_colsq[c] * (1.0f / N_NODES) - m * m;
        float rs = rsqrtf(va + BN_EPS);
        float sc = rs * gamma[c];
        ssc[c] = sc;
        ssh[c] = beta[c] - m * sc;
    }
    __syncthreads();
    int i = blockIdx.x * blockDim.x + threadIdx.x;
    if (i < N_NODES) g_cnt[i] = 0;     // invariant: cnt zeroed for next run
    if (i >= N_NODES * (D / 4)) return;
    int c4 = i & (D / 4 - 1);
    float4 y  = ((const float4*)g_y)[i];
    float4 hh = ((const float4*)h)[i];
    float4 o;
    o.x = hh.x + y.x * ssc[c4 * 4 + 0] + ssh[c4 * 4 + 0];
    o.y = hh.y + y.y * ssc[c4 * 4 + 1] + ssh[c4 * 4 + 1];
    o.z = hh.z + y.z * ssc[c4 * 4 + 2] + ssh[c4 * 4 + 2];
    o.w = hh.w + y.w * ssc[c4 * 4 + 3] + ssh[c4 * 4 + 3];
    ((float4*)out)[i] = o;
}

// ---------------- launch ----------------
extern "C" void kernel_launch(void* const* d_in, const int* in_sizes, int n_in,
                              void* d_out, int out_size) {
    const float* h      = (const float*)d_in[0];
    const float* snorm  = (const float*)d_in[1];
    const float* Ws     = (const float*)d_in[2];
    const float* Wn     = (const float*)d_in[3];
    const float* bias   = (const float*)d_in[4];
    const float* gamma  = (const float*)d_in[5];
    const float* beta   = (const float*)d_in[6];
    const int*   src    = (const int*)d_in[7];
    const int*   dst    = (const int*)d_in[8];
    float* out = (float*)d_out;

    cudaFuncSetAttribute(k_gemm_mma, cudaFuncAttributeMaxDynamicSharedMemorySize,
                         SM_TOTAL);

    int nd4_blocks = (N_NODES * (D / 4) + 255) / 256;   // 5000
    int edge_blocks = (N_EDGES + 255) / 256;            // 2500
    int node_blocks = (N_NODES + 255) / 256;            // 157

    k_prep<<<nd4_blocks, 256>>>(h, dst, Ws, Wn);
    k_scan<<<node_blocks, 256>>>();
    k_fill<<<edge_blocks, 256>>>(src, dst);
    k_gather<<<(N_NODES * 32 + 255) / 256, 256>>>();
    k_gemm_mma<<<GEMM_GRID, 256, SM_TOTAL>>>(h, bias, snorm);
    k_final<<<nd4_blocks, 256>>>(h, gamma, beta, out);
}

// round 14
// speedup vs baseline: 1.0187x; 1.0187x over previous
#include <cuda_runtime.h>
#include <cuda_fp16.h>
#include <cuda_bf16.h>
#include <cstdint>

#define N_NODES 40000
#define N_EDGES 640000
#define D 128
#define BN_EPS 1e-5f
#define KP 136   // padded K stride (bf16) -> conflict-free MMA frags

// ---------------- device scratch (no allocations allowed) ----------------
__device__ __half g_h16[(size_t)N_NODES * D];     // f16 copy of h (messages)
__device__ __nv_bfloat16 g_Ahi[(size_t)N_NODES * D];   // bf16 hi of h
__device__ __nv_bfloat16 g_Alo[(size_t)N_NODES * D];   // bf16 lo of h
__device__ __nv_bfloat16 g_hnhi[(size_t)N_NODES * D];  // bf16 hi of hneigh
__device__ __nv_bfloat16 g_hnlo[(size_t)N_NODES * D];  // bf16 lo of hneigh
__device__ float  g_y[(size_t)N_NODES * D];       // pre-batchnorm activations
__device__ int    g_cnt[N_NODES];                 // zero-init; re-zeroed by k_final
__device__ int    g_rowstart[N_NODES];
__device__ int    g_fill[N_NODES];
__device__ unsigned g_csr[N_EDGES];               // BYTE offsets of src rows (src<<8)
__device__ int    g_total;
__device__ float  g_colsum[D];
__device__ float  g_colsq[D];
__device__ __align__(16) __nv_bfloat16 g_Bw[2][2][128 * KP];

// ---------------- K1: prep: h->f16 + h->bf16 hi/lo, hist, W split --------
__global__ void __launch_bounds__(256) k_prep(const float* __restrict__ h,
                                              const int* __restrict__ dst,
                                              const float* __restrict__ Ws,
                                              const float* __restrict__ Wn) {
    int i = blockIdx.x * 256 + threadIdx.x;
    if (i < N_NODES * (D / 4)) {
        float4 v = ((const float4*)h)[i];
        // f16 messages
        __half2 m0 = __floats2half2_rn(v.x, v.y);
        __half2 m1 = __floats2half2_rn(v.z, v.w);
        ((uint2*)g_h16)[i] = make_uint2(*(unsigned*)&m0, *(unsigned*)&m1);
        // bf16 hi/lo split
        __nv_bfloat162 h0 = __floats2bfloat162_rn(v.x, v.y);
        __nv_bfloat162 h1 = __floats2bfloat162_rn(v.z, v.w);
        float2 f0 = __bfloat1622float2(h0);
        float2 f1 = __bfloat1622float2(h1);
        __nv_bfloat162 l0 = __floats2bfloat162_rn(v.x - f0.x, v.y - f0.y);
        __nv_bfloat162 l1 = __floats2bfloat162_rn(v.z - f1.x, v.w - f1.y);
        ((uint2*)g_Ahi)[i] = make_uint2(*(unsigned*)&h0, *(unsigned*)&h1);
        ((uint2*)g_Alo)[i] = make_uint2(*(unsigned*)&l0, *(unsigned*)&l1);
    }
    if (i < N_EDGES) atomicAdd(&g_cnt[dst[i]], 1);
    if (i < 2 * D * D) {                       // W^T hi/lo split images
        int chunk = i >> 14;
        int n = (i >> 7) & 127;
        int k = i & 127;
        float w = (chunk == 0 ? Ws : Wn)[k * D + n];
        __nv_bfloat16 hi = __float2bfloat16(w);
        __nv_bfloat16 lo = __float2bfloat16(w - __bfloat162float(hi));
        g_Bw[chunk][0][n * KP + k] = hi;
        g_Bw[chunk][1][n * KP + k] = lo;
    }
    if (i < D) { g_colsum[i] = 0.f; g_colsq[i] = 0.f; }
    if (i == 0) g_total = 0;
}

// ---------------- K2: scan; disjoint block bases via atomic --------------
__global__ void __launch_bounds__(256) k_scan() {
    __shared__ int wsum[8];
    __shared__ int sbase;
    int i = blockIdx.x * 256 + threadIdx.x;
    int lane = threadIdx.x & 31;
    int wd = threadIdx.x >> 5;
    int c = (i < N_NODES) ? g_cnt[i] : 0;
    int v = c;
    #pragma unroll
    for (int off = 1; off < 32; off <<= 1) {
        int t = __shfl_up_sync(0xFFFFFFFF, v, off);
        if (lane >= off) v += t;
    }
    if (lane == 31) wsum[wd] = v;
    __syncthreads();
    if (threadIdx.x < 8) {
        int ws = wsum[threadIdx.x];
        int p = ws;
        #pragma unroll
        for (int off = 1; off < 8; off <<= 1) {
            int t = __shfl_up_sync(0xFF, p, off);
            if ((int)threadIdx.x >= off) p += t;
        }
        wsum[threadIdx.x] = p - ws;
        if (threadIdx.x == 7) sbase = atomicAdd(&g_total, p);
    }
    __syncthreads();
    if (i < N_NODES) {
        int excl = sbase + wsum[wd] + v - c;
        g_rowstart[i] = excl;
        g_fill[i] = excl;
    }
}

// ---------------- K3: fill CSR (stores src byte offsets) -----------------
__global__ void __launch_bounds__(256) k_fill(const int* __restrict__ src,
                                              const int* __restrict__ dst) {
    int e = blockIdx.x * blockDim.x + threadIdx.x;
    if (e < N_EDGES) {
        int d = dst[e];
        int pos = atomicAdd(&g_fill[d], 1);
        g_csr[pos] = (unsigned)src[e] << 8;    // 256 B per h16 row
    }
}

// ---------------- K4: warp-per-node gather -> bf16 hi/lo output ----------
__device__ __forceinline__ void add8f(float* a, uint4 u) {
    float2 f;
    f = __half22float2(*(__half2*)&u.x); a[0] += f.x; a[1] += f.y;
    f = __half22float2(*(__half2*)&u.y); a[2] += f.x; a[3] += f.y;
    f = __half22float2(*(__half2*)&u.z); a[4] += f.x; a[5] += f.y;
    f = __half22float2(*(__half2*)&u.w); a[6] += f.x; a[7] += f.y;
}
__global__ void __launch_bounds__(256) k_gather() {
    int w = (blockIdx.x * 256 + threadIdx.x) >> 5;
    int lane = threadIdx.x & 31;
    if (w >= N_NODES) return;
    int rs  = g_rowstart[w];
    int deg = g_cnt[w];
    int hl = lane >> 4;            // half-group: neighbor parity
    int li = lane & 15;            // 16 lanes x uint4 = one 128-half row
    const char* base = (const char*)g_h16 + (unsigned)(li * 16);

    float acc[8] = {0.f, 0.f, 0.f, 0.f, 0.f, 0.f, 0.f, 0.f};
    int j = 0;
    for (; j + 4 <= deg; j += 4) {
        unsigned oA = g_csr[rs + j + hl];
        unsigned oB = g_csr[rs + j + 2 + hl];
        uint4 uA = *(const uint4*)(base + oA);
        uint4 uB = *(const uint4*)(base + oB);
        __half2 p0 = __hadd2(*(__half2*)&uA.x, *(__half2*)&uB.x);
        __half2 p1 = __hadd2(*(__half2*)&uA.y, *(__half2*)&uB.y);
        __half2 p2 = __hadd2(*(__half2*)&uA.z, *(__half2*)&uB.z);
        __half2 p3 = __hadd2(*(__half2*)&uA.w, *(__half2*)&uB.w);
        float2 f;
        f = __half22float2(p0); acc[0] += f.x; acc[1] += f.y;
        f = __half22float2(p1); acc[2] += f.x; acc[3] += f.y;
        f = __half22float2(p2); acc[4] += f.x; acc[5] += f.y;
        f = __half22float2(p3); acc[6] += f.x; acc[7] += f.y;
    }
    for (; j + 2 <= deg; j += 2) {
        unsigned oA = g_csr[rs + j + hl];
        add8f(acc, *(const uint4*)(base + oA));
    }
    if (j < deg && hl == 0) {
        unsigned oA = g_csr[rs + j];
        add8f(acc, *(const uint4*)(base + oA));
    }
    #pragma unroll
    for (int k = 0; k < 8; k++)
        acc[k] += __shfl_down_sync(0xFFFFFFFF, acc[k], 16);
    if (hl == 0) {
        float inv = 1.0f / fmaxf((float)deg, 1.0f);
        #pragma unroll
        for (int k = 0; k < 8; k++) acc[k] *= inv;
        __nv_bfloat162 h0 = __floats2bfloat162_rn(acc[0], acc[1]);
        __nv_bfloat162 h1 = __floats2bfloat162_rn(acc[2], acc[3]);
        __nv_bfloat162 h2 = __floats2bfloat162_rn(acc[4], acc[5]);
        __nv_bfloat162 h3 = __floats2bfloat162_rn(acc[6], acc[7]);
        float2 f0 = __bfloat1622float2(h0);
        float2 f1 = __bfloat1622float2(h1);
        float2 f2 = __bfloat1622float2(h2);
        float2 f3 = __bfloat1622float2(h3);
        __nv_bfloat162 l0 = __floats2bfloat162_rn(acc[0] - f0.x, acc[1] - f0.y);
        __nv_bfloat162 l1 = __floats2bfloat162_rn(acc[2] - f1.x, acc[3] - f1.y);
        __nv_bfloat162 l2 = __floats2bfloat162_rn(acc[4] - f2.x, acc[5] - f2.y);
        __nv_bfloat162 l3 = __floats2bfloat162_rn(acc[6] - f3.x, acc[7] - f3.y);
        ((uint4*)g_hnhi)[(size_t)w * 16 + li] =
            make_uint4(*(unsigned*)&h0, *(unsigned*)&h1, *(unsigned*)&h2, *(unsigned*)&h3);
        ((uint4*)g_hnlo)[(size_t)w * 16 + li] =
            make_uint4(*(unsigned*)&l0, *(unsigned*)&l1, *(unsigned*)&l2, *(unsigned*)&l3);
    }
}

// ---------------- K5: M=64 HMMA GEMM, copy-only staging (R11 best) -------
#define AT (64 * KP)                       // one A tile (elems)
#define BT (128 * KP)                      // one B tile (elems)
#define SM_TOTAL ((2 * AT + 2 * BT) * 2)   // bytes: 104448

__device__ __forceinline__ void mma_bf16(float* c, uint32_t a0, uint32_t a1,
                                         uint32_t a2, uint32_t a3,
                                         uint32_t b0, uint32_t b1) {
    asm volatile(
        "mma.sync.aligned.m16n8k16.row.col.f32.bf16.bf16.f32 "
        "{%0,%1,%2,%3}, {%4,%5,%6,%7}, {%8,%9}, {%0,%1,%2,%3};"
        : "+f"(c[0]), "+f"(c[1]), "+f"(c[2]), "+f"(c[3])
        : "r"(a0), "r"(a1), "r"(a2), "r"(a3), "r"(b0), "r"(b1));
}

__global__ void __launch_bounds__(256) k_gemm_mma(const float* __restrict__ bias,
                                                  const float* __restrict__ snorm) {
    extern __shared__ __align__(16) __nv_bfloat16 smem[];
    __nv_bfloat16* Ahi = smem;
    __nv_bfloat16* Alo = smem + AT;
    __nv_bfloat16* Bhi = smem + 2 * AT;
    __nv_bfloat16* Blo = smem + 2 * AT + BT;
    __shared__ float red[D];
    __shared__ float redq[D];

    const int tid = threadIdx.x;
    const int w   = tid >> 5;
    const int lane = tid & 31;
    const int g = lane >> 2;
    const int t = lane & 3;
    const int rt = w & 3;          // row-tile: rows rt*16 .. +16
    const int nh = w >> 2;         // col half: cols nh*64 .. +64
    const int row0 = blockIdx.x * 64;

    if (tid < D) { red[tid] = 0.f; redq[tid] = 0.f; }

    // A copy mapping: thread -> (hi/lo buf, row, 64-col half)
    const int abuf = tid >> 7;     // 0=hi, 1=lo
    const int aidx = tid & 127;
    const int ar   = aidx >> 1;    // row 0..63
    const int ahf  = aidx & 1;     // col half

    float acc[8][4];
    #pragma unroll
    for (int nt = 0; nt < 8; nt++)
        #pragma unroll
        for (int c = 0; c < 4; c++) acc[nt][c] = 0.f;

    for (int chunk = 0; chunk < 2; chunk++) {
        __syncthreads();
        // ---- stage A: pure 128B copy per thread ----
        {
            const __nv_bfloat16* gsrc = chunk
                ? (abuf ? g_hnlo : g_hnhi)
                : (abuf ? g_Alo : g_Ahi);
            const uint4* sp = (const uint4*)(gsrc + (size_t)(row0 + ar) * D + ahf * 64);
            uint4* dp = (uint4*)((abuf ? Alo : Ahi) + ar * KP + ahf * 64);
            #pragma unroll
            for (int i = 0; i < 8; i++) dp[i] = sp[i];
        }
        // ---- copy B hi+lo (69632 B contiguous) ----
        {
            const uint4* bsrc = (const uint4*)&g_Bw[chunk][0][0];
            uint4* bdst = (uint4*)Bhi;
            #pragma unroll
            for (int i = 0; i < 17; i++) bdst[tid + i * 256] = bsrc[tid + i * 256];
        }
        __syncthreads();

        // ---- pass 1: (Ahi + Alo) x Bhi ----
        #pragma unroll
        for (int ks = 0; ks < 8; ks++) {
            const int k0 = ks * 16;
            const __nv_bfloat16* ar0 = Ahi + (rt * 16 + g) * KP + k0 + t * 2;
            const __nv_bfloat16* ar1 = ar0 + 8 * KP;
            uint32_t ah0 = *(const uint32_t*)ar0;
            uint32_t ah2 = *(const uint32_t*)(ar0 + 8);
            uint32_t ah1 = *(const uint32_t*)ar1;
            uint32_t ah3 = *(const uint32_t*)(ar1 + 8);
            const __nv_bfloat16* al0p = Alo + (rt * 16 + g) * KP + k0 + t * 2;
            const __nv_bfloat16* al1p = al0p + 8 * KP;
            uint32_t al0 = *(const uint32_t*)al0p;
            uint32_t al2 = *(const uint32_t*)(al0p + 8);
            uint32_t al1 = *(const uint32_t*)al1p;
            uint32_t al3 = *(const uint32_t*)(al1p + 8);
            #pragma unroll
            for (int nt = 0; nt < 8; nt++) {
                const __nv_bfloat16* br = Bhi + ((nh * 8 + nt) * 8 + g) * KP + k0 + t * 2;
                uint32_t b0 = *(const uint32_t*)br;
                uint32_t b1 = *(const uint32_t*)(br + 8);
                mma_bf16(acc[nt], ah0, ah1, ah2, ah3, b0, b1);
                mma_bf16(acc[nt], al0, al1, al2, al3, b0, b1);
            }
        }
        // ---- pass 2: Ahi x Blo ----
        #pragma unroll
        for (int ks = 0; ks < 8; ks++) {
            const int k0 = ks * 16;
            const __nv_bfloat16* ar0 = Ahi + (rt * 16 + g) * KP + k0 + t * 2;
            const __nv_bfloat16* ar1 = ar0 + 8 * KP;
            uint32_t ah0 = *(const uint32_t*)ar0;
            uint32_t ah2 = *(const uint32_t*)(ar0 + 8);
            uint32_t ah1 = *(const uint32_t*)ar1;
            uint32_t ah3 = *(const uint32_t*)(ar1 + 8);
            #pragma unroll
            for (int nt = 0; nt < 8; nt++) {
                const __nv_bfloat16* br = Blo + ((nh * 8 + nt) * 8 + g) * KP + k0 + t * 2;
                uint32_t b0 = *(const uint32_t*)br;
                uint32_t b1 = *(const uint32_t*)(br + 8);
                mma_bf16(acc[nt], ah0, ah1, ah2, ah3, b0, b1);
            }
        }
    }

    // ---- epilogue: bias + relu + snorm -> g_y ; fused column stats ----
    {
        int rowa = row0 + rt * 16 + g;
        int rowb = rowa + 8;
        float sna = snorm[rowa];
        float snb = snorm[rowb];
        #pragma unroll
        for (int nt = 0; nt < 8; nt++) {
            int col = nh * 64 + nt * 8 + t * 2;
            float b0 = bias[col], b1 = bias[col + 1];
            float2 oa, ob;
            oa.x = fmaxf(acc[nt][0] + b0, 0.f) * sna;
            oa.y = fmaxf(acc[nt][1] + b1, 0.f) * sna;
            ob.x = fmaxf(acc[nt][2] + b0, 0.f) * snb;
            ob.y = fmaxf(acc[nt][3] + b1, 0.f) * snb;
            *(float2*)(g_y + (size_t)rowa * D + col) = oa;
            *(float2*)(g_y + (size_t)rowb * D + col) = ob;
            float s0 = oa.x + ob.x, s1 = oa.y + ob.y;
            float q0 = oa.x * oa.x + ob.x * ob.x, q1 = oa.y * oa.y + ob.y * ob.y;
            #pragma unroll
            for (int off = 16; off >= 4; off >>= 1) {
                s0 += __shfl_down_sync(0xFFFFFFFF, s0, off);
                s1 += __shfl_down_sync(0xFFFFFFFF, s1, off);
                q0 += __shfl_down_sync(0xFFFFFFFF, q0, off);
                q1 += __shfl_down_sync(0xFFFFFFFF, q1, off);
            }
            if (g == 0) {
                atomicAdd(&red[col], s0);
                atomicAdd(&red[col + 1], s1);
                atomicAdd(&redq[col], q0);
                atomicAdd(&redq[col + 1], q1);
            }
        }
    }
    __syncthreads();
    if (tid < D) {
        atomicAdd(&g_colsum[tid], red[tid]);
        atomicAdd(&g_colsq[tid], redq[tid]);
    }
}

// ---------------- K6: out = h + y*scale + shift ; re-zero g_cnt ----------
__global__ void __launch_bounds__(256) k_final(const float* __restrict__ h,
                                               const float* __restrict__ gamma,
                                               const float* __restrict__ beta,
                                               float* __restrict__ out) {
    __shared__ float ssc[D], ssh[D];
    if (threadIdx.x < D) {
        int c = threadIdx.x;
        float m  = g_colsum[c] * (1.0f / N_NODES);
        float va = g_colsq[c] * (1.0f / N_NODES) - m * m;
        float rs = rsqrtf(va + BN_EPS);
        float sc = rs * gamma[c];
        ssc[c] = sc;
        ssh[c] = beta[c] - m * sc;
    }
    __syncthreads();
    int i = blockIdx.x * blockDim.x + threadIdx.x;
    if (i < N_NODES) g_cnt[i] = 0;     // invariant: cnt zeroed for next run
    if (i >= N_NODES * (D / 4)) return;
    int c4 = i & (D / 4 - 1);
    float4 y  = ((const float4*)g_y)[i];
    float4 hh = ((const float4*)h)[i];
    float4 o;
    o.x = hh.x + y.x * ssc[c4 * 4 + 0] + ssh[c4 * 4 + 0];
    o.y = hh.y + y.y * ssc[c4 * 4 + 1] + ssh[c4 * 4 + 1];
    o.z = hh.z + y.z * ssc[c4 * 4 + 2] + ssh[c4 * 4 + 2];
    o.w = hh.w + y.w * ssc[c4 * 4 + 3] + ssh[c4 * 4 + 3];
    ((float4*)out)[i] = o;
}

// ---------------- launch ----------------
extern "C" void kernel_launch(void* const* d_in, const int* in_sizes, int n_in,
                              void* d_out, int out_size) {
    const float* h      = (const float*)d_in[0];
    const float* snorm  = (const float*)d_in[1];
    const float* Ws     = (const float*)d_in[2];
    const float* Wn     = (const float*)d_in[3];
    const float* bias   = (const float*)d_in[4];
    const float* gamma  = (const float*)d_in[5];
    const float* beta   = (const float*)d_in[6];
    const int*   src    = (const int*)d_in[7];
    const int*   dst    = (const int*)d_in[8];
    float* out = (float*)d_out;

    cudaFuncSetAttribute(k_gemm_mma, cudaFuncAttributeMaxDynamicSharedMemorySize,
                         SM_TOTAL);

    int nd4_blocks = (N_NODES * (D / 4) + 255) / 256;   // 5000
    int edge_blocks = (N_EDGES + 255) / 256;            // 2500
    int gemm_blocks = N_NODES / 64;                     // 625
    int node_blocks = (N_NODES + 255) / 256;            // 157

    k_prep<<<nd4_blocks, 256>>>(h, dst, Ws, Wn);
    k_scan<<<node_blocks, 256>>>();
    k_fill<<<edge_blocks, 256>>>(src, dst);
    k_gather<<<(N_NODES * 32 + 255) / 256, 256>>>();
    k_gemm_mma<<<gemm_blocks, 256, SM_TOTAL>>>(bias, snorm);
    k_final<<<nd4_blocks, 256>>>(h, gamma, beta, out);
}

// round 15
// speedup vs baseline: 1.0205x; 1.0018x over previous
#include <cuda_runtime.h>
#include <cuda_fp16.h>
#include <cuda_bf16.h>
#include <cstdint>

#define N_NODES 40000
#define N_EDGES 640000
#define D 128
#define BN_EPS 1e-5f
#define KP 136   // padded K stride (bf16) -> conflict-free MMA frags

// ---------------- device scratch (no allocations allowed) ----------------
__device__ __half g_h16[(size_t)N_NODES * D];     // f16 copy of h (messages)
__device__ __nv_bfloat16 g_Ahi[(size_t)N_NODES * D];   // bf16 hi of h
__device__ __nv_bfloat16 g_Alo[(size_t)N_NODES * D];   // bf16 lo of h
__device__ __nv_bfloat16 g_hnhi[(size_t)N_NODES * D];  // bf16 hi of hneigh
__device__ __nv_bfloat16 g_hnlo[(size_t)N_NODES * D];  // bf16 lo of hneigh
__device__ float  g_y[(size_t)N_NODES * D];       // pre-batchnorm activations
__device__ int    g_cnt[N_NODES];                 // zero-init; re-zeroed by k_final
__device__ int    g_rowstart[N_NODES];
__device__ int    g_fill[N_NODES];
__device__ int    g_csr[N_EDGES];                 // src node ids grouped by dst
__device__ int    g_total;
__device__ float  g_colsum[D];
__device__ float  g_colsq[D];
__device__ __align__(16) __nv_bfloat16 g_Bw[2][2][128 * KP];

// ---------------- K1: prep: h->f16 + h->bf16 hi/lo, hist, W split --------
__global__ void __launch_bounds__(256) k_prep(const float* __restrict__ h,
                                              const int* __restrict__ dst,
                                              const float* __restrict__ Ws,
                                              const float* __restrict__ Wn) {
    int i = blockIdx.x * 256 + threadIdx.x;
    if (i < N_NODES * (D / 4)) {
        float4 v = ((const float4*)h)[i];
        __half2 m0 = __floats2half2_rn(v.x, v.y);
        __half2 m1 = __floats2half2_rn(v.z, v.w);
        ((uint2*)g_h16)[i] = make_uint2(*(unsigned*)&m0, *(unsigned*)&m1);
        __nv_bfloat162 h0 = __floats2bfloat162_rn(v.x, v.y);
        __nv_bfloat162 h1 = __floats2bfloat162_rn(v.z, v.w);
        float2 f0 = __bfloat1622float2(h0);
        float2 f1 = __bfloat1622float2(h1);
        __nv_bfloat162 l0 = __floats2bfloat162_rn(v.x - f0.x, v.y - f0.y);
        __nv_bfloat162 l1 = __floats2bfloat162_rn(v.z - f1.x, v.w - f1.y);
        ((uint2*)g_Ahi)[i] = make_uint2(*(unsigned*)&h0, *(unsigned*)&h1);
        ((uint2*)g_Alo)[i] = make_uint2(*(unsigned*)&l0, *(unsigned*)&l1);
    }
    if (i < N_EDGES) atomicAdd(&g_cnt[dst[i]], 1);
    if (i < 2 * D * D) {                       // W^T hi/lo split images
        int chunk = i >> 14;
        int n = (i >> 7) & 127;
        int k = i & 127;
        float w = (chunk == 0 ? Ws : Wn)[k * D + n];
        __nv_bfloat16 hi = __float2bfloat16(w);
        __nv_bfloat16 lo = __float2bfloat16(w - __bfloat162float(hi));
        g_Bw[chunk][0][n * KP + k] = hi;
        g_Bw[chunk][1][n * KP + k] = lo;
    }
    if (i < D) { g_colsum[i] = 0.f; g_colsq[i] = 0.f; }
    if (i == 0) g_total = 0;
}

// ---------------- K2: scan; disjoint block bases via atomic --------------
__global__ void __launch_bounds__(256) k_scan() {
    __shared__ int wsum[8];
    __shared__ int sbase;
    int i = blockIdx.x * 256 + threadIdx.x;
    int lane = threadIdx.x & 31;
    int wd = threadIdx.x >> 5;
    int c = (i < N_NODES) ? g_cnt[i] : 0;
    int v = c;
    #pragma unroll
    for (int off = 1; off < 32; off <<= 1) {
        int t = __shfl_up_sync(0xFFFFFFFF, v, off);
        if (lane >= off) v += t;
    }
    if (lane == 31) wsum[wd] = v;
    __syncthreads();
    if (threadIdx.x < 8) {
        int ws = wsum[threadIdx.x];
        int p = ws;
        #pragma unroll
        for (int off = 1; off < 8; off <<= 1) {
            int t = __shfl_up_sync(0xFF, p, off);
            if ((int)threadIdx.x >= off) p += t;
        }
        wsum[threadIdx.x] = p - ws;
        if (threadIdx.x == 7) sbase = atomicAdd(&g_total, p);
    }
    __syncthreads();
    if (i < N_NODES) {
        int excl = sbase + wsum[wd] + v - c;
        g_rowstart[i] = excl;
        g_fill[i] = excl;
    }
}

// ---------------- K3: fill CSR ----------------
__global__ void __launch_bounds__(256) k_fill(const int* __restrict__ src,
                                              const int* __restrict__ dst) {
    int e = blockIdx.x * blockDim.x + threadIdx.x;
    if (e < N_EDGES) {
        int d = dst[e];
        int pos = atomicAdd(&g_fill[d], 1);
        g_csr[pos] = src[e];
    }
}

// ---------------- K4: gather with f16 accumulation -> bf16 hi/lo ---------
__global__ void __launch_bounds__(256) k_gather() {
    int w = (blockIdx.x * 256 + threadIdx.x) >> 5;
    int lane = threadIdx.x & 31;
    if (w >= N_NODES) return;
    int rs  = g_rowstart[w];
    int deg = g_cnt[w];
    int hl = lane >> 4;            // half-group: neighbor parity
    int li = lane & 15;            // 16 lanes x uint4 = one 128-half row
    const uint4* hp = (const uint4*)g_h16;

    __half2 a0 = __float2half2_rn(0.f);
    __half2 a1 = a0, a2 = a0, a3 = a0;
    int j = 0;
    for (; j + 4 <= deg; j += 4) {
        int sA = g_csr[rs + j + hl];
        int sB = g_csr[rs + j + 2 + hl];
        uint4 uA = hp[(size_t)sA * 16 + li];
        uint4 uB = hp[(size_t)sB * 16 + li];
        a0 = __hadd2(a0, __hadd2(*(__half2*)&uA.x, *(__half2*)&uB.x));
        a1 = __hadd2(a1, __hadd2(*(__half2*)&uA.y, *(__half2*)&uB.y));
        a2 = __hadd2(a2, __hadd2(*(__half2*)&uA.z, *(__half2*)&uB.z));
        a3 = __hadd2(a3, __hadd2(*(__half2*)&uA.w, *(__half2*)&uB.w));
    }
    for (; j + 2 <= deg; j += 2) {
        int sA = g_csr[rs + j + hl];
        uint4 uA = hp[(size_t)sA * 16 + li];
        a0 = __hadd2(a0, *(__half2*)&uA.x);
        a1 = __hadd2(a1, *(__half2*)&uA.y);
        a2 = __hadd2(a2, *(__half2*)&uA.z);
        a3 = __hadd2(a3, *(__half2*)&uA.w);
    }
    if (j < deg && hl == 0) {
        int sA = g_csr[rs + j];
        uint4 uA = hp[(size_t)sA * 16 + li];
        a0 = __hadd2(a0, *(__half2*)&uA.x);
        a1 = __hadd2(a1, *(__half2*)&uA.y);
        a2 = __hadd2(a2, *(__half2*)&uA.z);
        a3 = __hadd2(a3, *(__half2*)&uA.w);
    }
    // convert once, then combine the two half-groups in fp32
    float acc[8];
    {
        float2 f;
        f = __half22float2(a0); acc[0] = f.x; acc[1] = f.y;
        f = __half22float2(a1); acc[2] = f.x; acc[3] = f.y;
        f = __half22float2(a2); acc[4] = f.x; acc[5] = f.y;
        f = __half22float2(a3); acc[6] = f.x; acc[7] = f.y;
    }
    #pragma unroll
    for (int k = 0; k < 8; k++)
        acc[k] += __shfl_down_sync(0xFFFFFFFF, acc[k], 16);
    if (hl == 0) {
        float inv = 1.0f / fmaxf((float)deg, 1.0f);
        #pragma unroll
        for (int k = 0; k < 8; k++) acc[k] *= inv;
        __nv_bfloat162 h0 = __floats2bfloat162_rn(acc[0], acc[1]);
        __nv_bfloat162 h1 = __floats2bfloat162_rn(acc[2], acc[3]);
        __nv_bfloat162 h2 = __floats2bfloat162_rn(acc[4], acc[5]);
        __nv_bfloat162 h3 = __floats2bfloat162_rn(acc[6], acc[7]);
        float2 f0 = __bfloat1622float2(h0);
        float2 f1 = __bfloat1622float2(h1);
        float2 f2 = __bfloat1622float2(h2);
        float2 f3 = __bfloat1622float2(h3);
        __nv_bfloat162 l0 = __floats2bfloat162_rn(acc[0] - f0.x, acc[1] - f0.y);
        __nv_bfloat162 l1 = __floats2bfloat162_rn(acc[2] - f1.x, acc[3] - f1.y);
        __nv_bfloat162 l2 = __floats2bfloat162_rn(acc[4] - f2.x, acc[5] - f2.y);
        __nv_bfloat162 l3 = __floats2bfloat162_rn(acc[6] - f3.x, acc[7] - f3.y);
        ((uint4*)g_hnhi)[(size_t)w * 16 + li] =
            make_uint4(*(unsigned*)&h0, *(unsigned*)&h1, *(unsigned*)&h2, *(unsigned*)&h3);
        ((uint4*)g_hnlo)[(size_t)w * 16 + li] =
            make_uint4(*(unsigned*)&l0, *(unsigned*)&l1, *(unsigned*)&l2, *(unsigned*)&l3);
    }
}

// ---------------- K5: M=64 HMMA GEMM, copy-only staging (R11 best) -------
#define AT (64 * KP)                       // one A tile (elems)
#define BT (128 * KP)                      // one B tile (elems)
#define SM_TOTAL ((2 * AT + 2 * BT) * 2)   // bytes: 104448

__device__ __forceinline__ void mma_bf16(float* c, uint32_t a0, uint32_t a1,
                                         uint32_t a2, uint32_t a3,
                                         uint32_t b0, uint32_t b1) {
    asm volatile(
        "mma.sync.aligned.m16n8k16.row.col.f32.bf16.bf16.f32 "
        "{%0,%1,%2,%3}, {%4,%5,%6,%7}, {%8,%9}, {%0,%1,%2,%3};"
        : "+f"(c[0]), "+f"(c[1]), "+f"(c[2]), "+f"(c[3])
        : "r"(a0), "r"(a1), "r"(a2), "r"(a3), "r"(b0), "r"(b1));
}

__global__ void __launch_bounds__(256) k_gemm_mma(const float* __restrict__ bias,
                                                  const float* __restrict__ snorm) {
    extern __shared__ __align__(16) __nv_bfloat16 smem[];
    __nv_bfloat16* Ahi = smem;
    __nv_bfloat16* Alo = smem + AT;
    __nv_bfloat16* Bhi = smem + 2 * AT;
    __nv_bfloat16* Blo = smem + 2 * AT + BT;
    __shared__ float red[D];
    __shared__ float redq[D];

    const int tid = threadIdx.x;
    const int w   = tid >> 5;
    const int lane = tid & 31;
    const int g = lane >> 2;
    const int t = lane & 3;
    const int rt = w & 3;          // row-tile: rows rt*16 .. +16
    const int nh = w >> 2;         // col half: cols nh*64 .. +64
    const int row0 = blockIdx.x * 64;

    if (tid < D) { red[tid] = 0.f; redq[tid] = 0.f; }

    const int abuf = tid >> 7;     // 0=hi, 1=lo
    const int aidx = tid & 127;
    const int ar   = aidx >> 1;    // row 0..63
    const int ahf  = aidx & 1;     // col half

    float acc[8][4];
    #pragma unroll
    for (int nt = 0; nt < 8; nt++)
        #pragma unroll
        for (int c = 0; c < 4; c++) acc[nt][c] = 0.f;

    for (int chunk = 0; chunk < 2; chunk++) {
        __syncthreads();
        // ---- stage A: pure 128B copy per thread ----
        {
            const __nv_bfloat16* gsrc = chunk
                ? (abuf ? g_hnlo : g_hnhi)
                : (abuf ? g_Alo : g_Ahi);
            const uint4* sp = (const uint4*)(gsrc + (size_t)(row0 + ar) * D + ahf * 64);
            uint4* dp = (uint4*)((abuf ? Alo : Ahi) + ar * KP + ahf * 64);
            #pragma unroll
            for (int i = 0; i < 8; i++) dp[i] = sp[i];
        }
        // ---- copy B hi+lo (69632 B contiguous) ----
        {
            const uint4* bsrc = (const uint4*)&g_Bw[chunk][0][0];
            uint4* bdst = (uint4*)Bhi;
            #pragma unroll
            for (int i = 0; i < 17; i++) bdst[tid + i * 256] = bsrc[tid + i * 256];
        }
        __syncthreads();

        // ---- pass 1: (Ahi + Alo) x Bhi ----
        #pragma unroll
        for (int ks = 0; ks < 8; ks++) {
            const int k0 = ks * 16;
            const __nv_bfloat16* ar0 = Ahi + (rt * 16 + g) * KP + k0 + t * 2;
            const __nv_bfloat16* ar1 = ar0 + 8 * KP;
            uint32_t ah0 = *(const uint32_t*)ar0;
            uint32_t ah2 = *(const uint32_t*)(ar0 + 8);
            uint32_t ah1 = *(const uint32_t*)ar1;
            uint32_t ah3 = *(const uint32_t*)(ar1 + 8);
            const __nv_bfloat16* al0p = Alo + (rt * 16 + g) * KP + k0 + t * 2;
            const __nv_bfloat16* al1p = al0p + 8 * KP;
            uint32_t al0 = *(const uint32_t*)al0p;
            uint32_t al2 = *(const uint32_t*)(al0p + 8);
            uint32_t al1 = *(const uint32_t*)al1p;
            uint32_t al3 = *(const uint32_t*)(al1p + 8);
            #pragma unroll
            for (int nt = 0; nt < 8; nt++) {
                const __nv_bfloat16* br = Bhi + ((nh * 8 + nt) * 8 + g) * KP + k0 + t * 2;
                uint32_t b0 = *(const uint32_t*)br;
                uint32_t b1 = *(const uint32_t*)(br + 8);
                mma_bf16(acc[nt], ah0, ah1, ah2, ah3, b0, b1);
                mma_bf16(acc[nt], al0, al1, al2, al3, b0, b1);
            }
        }
        // ---- pass 2: Ahi x Blo ----
        #pragma unroll
        for (int ks = 0; ks < 8; ks++) {
            const int k0 = ks * 16;
            const __nv_bfloat16* ar0 = Ahi + (rt * 16 + g) * KP + k0 + t * 2;
            const __nv_bfloat16* ar1 = ar0 + 8 * KP;
            uint32_t ah0 = *(const uint32_t*)ar0;
            uint32_t ah2 = *(const uint32_t*)(ar0 + 8);
            uint32_t ah1 = *(const uint32_t*)ar1;
            uint32_t ah3 = *(const uint32_t*)(ar1 + 8);
            #pragma unroll
            for (int nt = 0; nt < 8; nt++) {
                const __nv_bfloat16* br = Blo + ((nh * 8 + nt) * 8 + g) * KP + k0 + t * 2;
                uint32_t b0 = *(const uint32_t*)br;
                uint32_t b1 = *(const uint32_t*)(br + 8);
                mma_bf16(acc[nt], ah0, ah1, ah2, ah3, b0, b1);
            }
        }
    }

    // ---- epilogue: bias + relu + snorm -> g_y ; fused column stats ----
    {
        int rowa = row0 + rt * 16 + g;
        int rowb = rowa + 8;
        float sna = snorm[rowa];
        float snb = snorm[rowb];
        #pragma unroll
        for (int nt = 0; nt < 8; nt++) {
            int col = nh * 64 + nt * 8 + t * 2;
            float b0 = bias[col], b1 = bias[col + 1];
            float2 oa, ob;
            oa.x = fmaxf(acc[nt][0] + b0, 0.f) * sna;
            oa.y = fmaxf(acc[nt][1] + b1, 0.f) * sna;
            ob.x = fmaxf(acc[nt][2] + b0, 0.f) * snb;
            ob.y = fmaxf(acc[nt][3] + b1, 0.f) * snb;
            *(float2*)(g_y + (size_t)rowa * D + col) = oa;
            *(float2*)(g_y + (size_t)rowb * D + col) = ob;
            float s0 = oa.x + ob.x, s1 = oa.y + ob.y;
            float q0 = oa.x * oa.x + ob.x * ob.x, q1 = oa.y * oa.y + ob.y * ob.y;
            #pragma unroll
            for (int off = 16; off >= 4; off >>= 1) {
                s0 += __shfl_down_sync(0xFFFFFFFF, s0, off);
                s1 += __shfl_down_sync(0xFFFFFFFF, s1, off);
                q0 += __shfl_down_sync(0xFFFFFFFF, q0, off);
                q1 += __shfl_down_sync(0xFFFFFFFF, q1, off);
            }
            if (g == 0) {
                atomicAdd(&red[col], s0);
                atomicAdd(&red[col + 1], s1);
                atomicAdd(&redq[col], q0);
                atomicAdd(&redq[col + 1], q1);
            }
        }
    }
    __syncthreads();
    if (tid < D) {
        atomicAdd(&g_colsum[tid], red[tid]);
        atomicAdd(&g_colsq[tid], redq[tid]);
    }
}

// ---------------- K6: out = h + y*scale + shift ; re-zero g_cnt ----------
__global__ void __launch_bounds__(256) k_final(const float* __restrict__ h,
                                               const float* __restrict__ gamma,
                                               const float* __restrict__ beta,
                                               float* __restrict__ out) {
    __shared__ float ssc[D], ssh[D];
    if (threadIdx.x < D) {
        int c = threadIdx.x;
        float m  = g_colsum[c] * (1.0f / N_NODES);
        float va = g_colsq[c] * (1.0f / N_NODES) - m * m;
        float rs = rsqrtf(va + BN_EPS);
        float sc = rs * gamma[c];
        ssc[c] = sc;
        ssh[c] = beta[c] - m * sc;
    }
    __syncthreads();
    int i = blockIdx.x * blockDim.x + threadIdx.x;
    if (i < N_NODES) g_cnt[i] = 0;     // invariant: cnt zeroed for next run
    if (i >= N_NODES * (D / 4)) return;
    int c4 = i & (D / 4 - 1);
    float4 y  = ((const float4*)g_y)[i];
    float4 hh = ((const float4*)h)[i];
    float4 o;
    o.x = hh.x + y.x * ssc[c4 * 4 + 0] + ssh[c4 * 4 + 0];
    o.y = hh.y + y.y * ssc[c4 * 4 + 1] + ssh[c4 * 4 + 1];
    o.z = hh.z + y.z * ssc[c4 * 4 + 2] + ssh[c4 * 4 + 2];
    o.w = hh.w + y.w * ssc[c4 * 4 + 3] + ssh[c4 * 4 + 3];
    ((float4*)out)[i] = o;
}

// ---------------- launch ----------------
extern "C" void kernel_launch(void* const* d_in, const int* in_sizes, int n_in,
                              void* d_out, int out_size) {
    const float* h      = (const float*)d_in[0];
    const float* snorm  = (const float*)d_in[1];
    const float* Ws     = (const float*)d_in[2];
    const float* Wn     = (const float*)d_in[3];
    const float* bias   = (const float*)d_in[4];
    const float* gamma  = (const float*)d_in[5];
    const float* beta   = (const float*)d_in[6];
    const int*   src    = (const int*)d_in[7];
    const int*   dst    = (const int*)d_in[8];
    float* out = (float*)d_out;

    cudaFuncSetAttribute(k_gemm_mma, cudaFuncAttributeMaxDynamicSharedMemorySize,
                         SM_TOTAL);

    int nd4_blocks = (N_NODES * (D / 4) + 255) / 256;   // 5000
    int edge_blocks = (N_EDGES + 255) / 256;            // 2500
    int gemm_blocks = N_NODES / 64;                     // 625
    int node_blocks = (N_NODES + 255) / 256;            // 157

    k_prep<<<nd4_blocks, 256>>>(h, dst, Ws, Wn);
    k_scan<<<node_blocks, 256>>>();
    k_fill<<<edge_blocks, 256>>>(src, dst);
    k_gather<<<(N_NODES * 32 + 255) / 256, 256>>>();
    k_gemm_mma<<<gemm_blocks, 256, SM_TOTAL>>>(bias, snorm);
    k_final<<<nd4_blocks, 256>>>(h, gamma, beta, out);
}

// round 16
// speedup vs baseline: 1.0404x; 1.0194x over previous
#include <cuda_runtime.h>
#include <cuda_fp16.h>
#include <cuda_bf16.h>
#include <cstdint>

#define N_NODES 40000
#define N_EDGES 640000
#define D 128
#define BN_EPS 1e-5f
#define KP 136   // padded K stride (bf16) -> conflict-free MMA frags

// ---------------- device scratch (no allocations allowed) ----------------
__device__ __half g_h16[(size_t)N_NODES * D];     // f16 copy of h (messages)
__device__ __nv_bfloat16 g_hnhi[(size_t)N_NODES * D];  // bf16 hi of hneigh
__device__ __nv_bfloat16 g_hnlo[(size_t)N_NODES * D];  // bf16 lo of hneigh
__device__ float  g_y[(size_t)N_NODES * D];       // pre-batchnorm activations
__device__ int    g_cnt[N_NODES];                 // zero-init; re-zeroed by k_final
__device__ int    g_rowstart[N_NODES];
__device__ int    g_fill[N_NODES];
__device__ int    g_csr[N_EDGES];                 // src node ids grouped by dst
__device__ int    g_total;
__device__ float  g_colsum[D];
__device__ float  g_colsq[D];
__device__ __align__(16) __nv_bfloat16 g_Bw[2][2][128 * KP];

// ---------------- K1: prep: h->f16, hist, W split, zero stats ------------
__global__ void __launch_bounds__(256) k_prep(const float* __restrict__ h,
                                              const int* __restrict__ dst,
                                              const float* __restrict__ Ws,
                                              const float* __restrict__ Wn) {
    int i = blockIdx.x * 256 + threadIdx.x;
    if (i < N_NODES * (D / 4)) {
        float4 v = ((const float4*)h)[i];
        __half2 m0 = __floats2half2_rn(v.x, v.y);
        __half2 m1 = __floats2half2_rn(v.z, v.w);
        ((uint2*)g_h16)[i] = make_uint2(*(unsigned*)&m0, *(unsigned*)&m1);
    }
    if (i < N_EDGES) atomicAdd(&g_cnt[dst[i]], 1);
    if (i < 2 * D * D) {                       // W^T hi/lo split images
        int chunk = i >> 14;
        int n = (i >> 7) & 127;
        int k = i & 127;
        float w = (chunk == 0 ? Ws : Wn)[k * D + n];
        __nv_bfloat16 hi = __float2bfloat16(w);
        __nv_bfloat16 lo = __float2bfloat16(w - __bfloat162float(hi));
        g_Bw[chunk][0][n * KP + k] = hi;
        g_Bw[chunk][1][n * KP + k] = lo;
    }
    if (i < D) { g_colsum[i] = 0.f; g_colsq[i] = 0.f; }
    if (i == 0) g_total = 0;
}

// ---------------- K2: scan; disjoint block bases via atomic --------------
__global__ void __launch_bounds__(256) k_scan() {
    __shared__ int wsum[8];
    __shared__ int sbase;
    int i = blockIdx.x * 256 + threadIdx.x;
    int lane = threadIdx.x & 31;
    int wd = threadIdx.x >> 5;
    int c = (i < N_NODES) ? g_cnt[i] : 0;
    int v = c;
    #pragma unroll
    for (int off = 1; off < 32; off <<= 1) {
        int t = __shfl_up_sync(0xFFFFFFFF, v, off);
        if (lane >= off) v += t;
    }
    if (lane == 31) wsum[wd] = v;
    __syncthreads();
    if (threadIdx.x < 8) {
        int ws = wsum[threadIdx.x];
        int p = ws;
        #pragma unroll
        for (int off = 1; off < 8; off <<= 1) {
            int t = __shfl_up_sync(0xFF, p, off);
            if ((int)threadIdx.x >= off) p += t;
        }
        wsum[threadIdx.x] = p - ws;
        if (threadIdx.x == 7) sbase = atomicAdd(&g_total, p);
    }
    __syncthreads();
    if (i < N_NODES) {
        int excl = sbase + wsum[wd] + v - c;
        g_rowstart[i] = excl;
        g_fill[i] = excl;
    }
}

// ---------------- K3: fill CSR ----------------
__global__ void __launch_bounds__(256) k_fill(const int* __restrict__ src,
                                              const int* __restrict__ dst) {
    int e = blockIdx.x * blockDim.x + threadIdx.x;
    if (e < N_EDGES) {
        int d = dst[e];
        int pos = atomicAdd(&g_fill[d], 1);
        g_csr[pos] = src[e];
    }
}

// ---------------- K4: gather with f16 accumulation -> bf16 hi/lo ---------
__global__ void __launch_bounds__(256) k_gather() {
    int w = (blockIdx.x * 256 + threadIdx.x) >> 5;
    int lane = threadIdx.x & 31;
    if (w >= N_NODES) return;
    int rs  = g_rowstart[w];
    int deg = g_cnt[w];
    int hl = lane >> 4;            // half-group: neighbor parity
    int li = lane & 15;            // 16 lanes x uint4 = one 128-half row
    const uint4* hp = (const uint4*)g_h16;

    __half2 a0 = __float2half2_rn(0.f);
    __half2 a1 = a0, a2 = a0, a3 = a0;
    int j = 0;
    for (; j + 4 <= deg; j += 4) {
        int sA = g_csr[rs + j + hl];
        int sB = g_csr[rs + j + 2 + hl];
        uint4 uA = hp[(size_t)sA * 16 + li];
        uint4 uB = hp[(size_t)sB * 16 + li];
        a0 = __hadd2(a0, __hadd2(*(__half2*)&uA.x, *(__half2*)&uB.x));
        a1 = __hadd2(a1, __hadd2(*(__half2*)&uA.y, *(__half2*)&uB.y));
        a2 = __hadd2(a2, __hadd2(*(__half2*)&uA.z, *(__half2*)&uB.z));
        a3 = __hadd2(a3, __hadd2(*(__half2*)&uA.w, *(__half2*)&uB.w));
    }
    for (; j + 2 <= deg; j += 2) {
        int sA = g_csr[rs + j + hl];
        uint4 uA = hp[(size_t)sA * 16 + li];
        a0 = __hadd2(a0, *(__half2*)&uA.x);
        a1 = __hadd2(a1, *(__half2*)&uA.y);
        a2 = __hadd2(a2, *(__half2*)&uA.z);
        a3 = __hadd2(a3, *(__half2*)&uA.w);
    }
    if (j < deg && hl == 0) {
        int sA = g_csr[rs + j];
        uint4 uA = hp[(size_t)sA * 16 + li];
        a0 = __hadd2(a0, *(__half2*)&uA.x);
        a1 = __hadd2(a1, *(__half2*)&uA.y);
        a2 = __hadd2(a2, *(__half2*)&uA.z);
        a3 = __hadd2(a3, *(__half2*)&uA.w);
    }
    float acc[8];
    {
        float2 f;
        f = __half22float2(a0); acc[0] = f.x; acc[1] = f.y;
        f = __half22float2(a1); acc[2] = f.x; acc[3] = f.y;
        f = __half22float2(a2); acc[4] = f.x; acc[5] = f.y;
        f = __half22float2(a3); acc[6] = f.x; acc[7] = f.y;
    }
    #pragma unroll
    for (int k = 0; k < 8; k++)
        acc[k] += __shfl_down_sync(0xFFFFFFFF, acc[k], 16);
    if (hl == 0) {
        float inv = 1.0f / fmaxf((float)deg, 1.0f);
        #pragma unroll
        for (int k = 0; k < 8; k++) acc[k] *= inv;
        __nv_bfloat162 h0 = __floats2bfloat162_rn(acc[0], acc[1]);
        __nv_bfloat162 h1 = __floats2bfloat162_rn(acc[2], acc[3]);
        __nv_bfloat162 h2 = __floats2bfloat162_rn(acc[4], acc[5]);
        __nv_bfloat162 h3 = __floats2bfloat162_rn(acc[6], acc[7]);
        float2 f0 = __bfloat1622float2(h0);
        float2 f1 = __bfloat1622float2(h1);
        float2 f2 = __bfloat1622float2(h2);
        float2 f3 = __bfloat1622float2(h3);
        __nv_bfloat162 l0 = __floats2bfloat162_rn(acc[0] - f0.x, acc[1] - f0.y);
        __nv_bfloat162 l1 = __floats2bfloat162_rn(acc[2] - f1.x, acc[3] - f1.y);
        __nv_bfloat162 l2 = __floats2bfloat162_rn(acc[4] - f2.x, acc[5] - f2.y);
        __nv_bfloat162 l3 = __floats2bfloat162_rn(acc[6] - f3.x, acc[7] - f3.y);
        ((uint4*)g_hnhi)[(size_t)w * 16 + li] =
            make_uint4(*(unsigned*)&h0, *(unsigned*)&h1, *(unsigned*)&h2, *(unsigned*)&h3);
        ((uint4*)g_hnlo)[(size_t)w * 16 + li] =
            make_uint4(*(unsigned*)&l0, *(unsigned*)&l1, *(unsigned*)&l2, *(unsigned*)&l3);
    }
}

// ---------------- K5: M=64 HMMA GEMM; chunk0 converts h in staging -------
#define AT (64 * KP)                       // one A tile (elems)
#define BT (128 * KP)                      // one B tile (elems)
#define SM_TOTAL ((2 * AT + 2 * BT) * 2)   // bytes: 104448

__device__ __forceinline__ void mma_bf16(float* c, uint32_t a0, uint32_t a1,
                                         uint32_t a2, uint32_t a3,
                                         uint32_t b0, uint32_t b1) {
    asm volatile(
        "mma.sync.aligned.m16n8k16.row.col.f32.bf16.bf16.f32 "
        "{%0,%1,%2,%3}, {%4,%5,%6,%7}, {%8,%9}, {%0,%1,%2,%3};"
        : "+f"(c[0]), "+f"(c[1]), "+f"(c[2]), "+f"(c[3])
        : "r"(a0), "r"(a1), "r"(a2), "r"(a3), "r"(b0), "r"(b1));
}

__global__ void __launch_bounds__(256) k_gemm_mma(const float* __restrict__ h,
                                                  const float* __restrict__ bias,
                                                  const float* __restrict__ snorm) {
    extern __shared__ __align__(16) __nv_bfloat16 smem[];
    __nv_bfloat16* Ahi = smem;
    __nv_bfloat16* Alo = smem + AT;
    __nv_bfloat16* Bhi = smem + 2 * AT;
    __nv_bfloat16* Blo = smem + 2 * AT + BT;
    __shared__ float red[D];
    __shared__ float redq[D];

    const int tid = threadIdx.x;
    const int w   = tid >> 5;
    const int lane = tid & 31;
    const int g = lane >> 2;
    const int t = lane & 3;
    const int rt = w & 3;          // row-tile: rows rt*16 .. +16
    const int nh = w >> 2;         // col half: cols nh*64 .. +64
    const int row0 = blockIdx.x * 64;

    if (tid < D) { red[tid] = 0.f; redq[tid] = 0.f; }

    float acc[8][4];
    #pragma unroll
    for (int nt = 0; nt < 8; nt++)
        #pragma unroll
        for (int c = 0; c < 4; c++) acc[nt][c] = 0.f;

    for (int chunk = 0; chunk < 2; chunk++) {
        __syncthreads();
        // ---- stage A ----
        if (chunk == 0) {
            // convert h fp32 -> bf16 hi/lo in registers during staging
            int arow = tid >> 2;           // 0..63
            int q = tid & 3;               // 32-col quarter
            const float4* sp = (const float4*)(h + (size_t)(row0 + arow) * D + q * 32);
            __nv_bfloat16* ah = Ahi + arow * KP + q * 32;
            __nv_bfloat16* al = Alo + arow * KP + q * 32;
            #pragma unroll
            for (int i = 0; i < 8; i++) {
                float4 v = sp[i];
                __nv_bfloat162 h0 = __floats2bfloat162_rn(v.x, v.y);
                __nv_bfloat162 h1 = __floats2bfloat162_rn(v.z, v.w);
                float2 f0 = __bfloat1622float2(h0);
                float2 f1 = __bfloat1622float2(h1);
                __nv_bfloat162 l0 = __floats2bfloat162_rn(v.x - f0.x, v.y - f0.y);
                __nv_bfloat162 l1 = __floats2bfloat162_rn(v.z - f1.x, v.w - f1.y);
                *(uint2*)(ah + i * 4) = make_uint2(*(uint32_t*)&h0, *(uint32_t*)&h1);
                *(uint2*)(al + i * 4) = make_uint2(*(uint32_t*)&l0, *(uint32_t*)&l1);
            }
        } else {
            // pure 128B copy of pre-split hneigh
            int abuf = tid >> 7;           // 0=hi, 1=lo
            int aidx = tid & 127;
            int arow = aidx >> 1;
            int ahf = aidx & 1;
            const __nv_bfloat16* gsrc = abuf ? g_hnlo : g_hnhi;
            const uint4* sp = (const uint4*)(gsrc + (size_t)(row0 + arow) * D + ahf * 64);
            uint4* dp = (uint4*)((abuf ? Alo : Ahi) + arow * KP + ahf * 64);
            #pragma unroll
            for (int i = 0; i < 8; i++) dp[i] = sp[i];
        }
        // ---- copy B hi+lo (69632 B contiguous) ----
        {
            const uint4* bsrc = (const uint4*)&g_Bw[chunk][0][0];
            uint4* bdst = (uint4*)Bhi;
            #pragma unroll
            for (int i = 0; i < 17; i++) bdst[tid + i * 256] = bsrc[tid + i * 256];
        }
        __syncthreads();

        // ---- pass 1: (Ahi + Alo) x Bhi ----
        #pragma unroll
        for (int ks = 0; ks < 8; ks++) {
            const int k0 = ks * 16;
            const __nv_bfloat16* ar0 = Ahi + (rt * 16 + g) * KP + k0 + t * 2;
            const __nv_bfloat16* ar1 = ar0 + 8 * KP;
            uint32_t ah0 = *(const uint32_t*)ar0;
            uint32_t ah2 = *(const uint32_t*)(ar0 + 8);
            uint32_t ah1 = *(const uint32_t*)ar1;
            uint32_t ah3 = *(const uint32_t*)(ar1 + 8);
            const __nv_bfloat16* al0p = Alo + (rt * 16 + g) * KP + k0 + t * 2;
            const __nv_bfloat16* al1p = al0p + 8 * KP;
            uint32_t al0 = *(const uint32_t*)al0p;
            uint32_t al2 = *(const uint32_t*)(al0p + 8);
            uint32_t al1 = *(const uint32_t*)al1p;
            uint32_t al3 = *(const uint32_t*)(al1p + 8);
            #pragma unroll
            for (int nt = 0; nt < 8; nt++) {
                const __nv_bfloat16* br = Bhi + ((nh * 8 + nt) * 8 + g) * KP + k0 + t * 2;
                uint32_t b0 = *(const uint32_t*)br;
                uint32_t b1 = *(const uint32_t*)(br + 8);
                mma_bf16(acc[nt], ah0, ah1, ah2, ah3, b0, b1);
                mma_bf16(acc[nt], al0, al1, al2, al3, b0, b1);
            }
        }
        // ---- pass 2: Ahi x Blo ----
        #pragma unroll
        for (int ks = 0; ks < 8; ks++) {
            const int k0 = ks * 16;
            const __nv_bfloat16* ar0 = Ahi + (rt * 16 + g) * KP + k0 + t * 2;
            const __nv_bfloat16* ar1 = ar0 + 8 * KP;
            uint32_t ah0 = *(const uint32_t*)ar0;
            uint32_t ah2 = *(const uint32_t*)(ar0 + 8);
            uint32_t ah1 = *(const uint32_t*)ar1;
            uint32_t ah3 = *(const uint32_t*)(ar1 + 8);
            #pragma unroll
            for (int nt = 0; nt < 8; nt++) {
                const __nv_bfloat16* br = Blo + ((nh * 8 + nt) * 8 + g) * KP + k0 + t * 2;
                uint32_t b0 = *(const uint32_t*)br;
                uint32_t b1 = *(const uint32_t*)(br + 8);
                mma_bf16(acc[nt], ah0, ah1, ah2, ah3, b0, b1);
            }
        }
    }

    // ---- epilogue: bias + relu + snorm -> g_y ; fused column stats ----
    {
        int rowa = row0 + rt * 16 + g;
        int rowb = rowa + 8;
        float sna = snorm[rowa];
        float snb = snorm[rowb];
        #pragma unroll
        for (int nt = 0; nt < 8; nt++) {
            int col = nh * 64 + nt * 8 + t * 2;
            float b0 = bias[col], b1 = bias[col + 1];
            float2 oa, ob;
            oa.x = fmaxf(acc[nt][0] + b0, 0.f) * sna;
            oa.y = fmaxf(acc[nt][1] + b1, 0.f) * sna;
            ob.x = fmaxf(acc[nt][2] + b0, 0.f) * snb;
            ob.y = fmaxf(acc[nt][3] + b1, 0.f) * snb;
            *(float2*)(g_y + (size_t)rowa * D + col) = oa;
            *(float2*)(g_y + (size_t)rowb * D + col) = ob;
            float s0 = oa.x + ob.x, s1 = oa.y + ob.y;
            float q0 = oa.x * oa.x + ob.x * ob.x, q1 = oa.y * oa.y + ob.y * ob.y;
            #pragma unroll
            for (int off = 16; off >= 4; off >>= 1) {
                s0 += __shfl_down_sync(0xFFFFFFFF, s0, off);
                s1 += __shfl_down_sync(0xFFFFFFFF, s1, off);
                q0 += __shfl_down_sync(0xFFFFFFFF, q0, off);
                q1 += __shfl_down_sync(0xFFFFFFFF, q1, off);
            }
            if (g == 0) {
                atomicAdd(&red[col], s0);
                atomicAdd(&red[col + 1], s1);
                atomicAdd(&redq[col], q0);
                atomicAdd(&redq[col + 1], q1);
            }
        }
    }
    __syncthreads();
    if (tid < D) {
        atomicAdd(&g_colsum[tid], red[tid]);
        atomicAdd(&g_colsq[tid], redq[tid]);
    }
}

// ---------------- K6: out = h + y*scale + shift ; re-zero g_cnt ----------
__global__ void __launch_bounds__(256) k_final(const float* __restrict__ h,
                                               const float* __restrict__ gamma,
                                               const float* __restrict__ beta,
                                               float* __restrict__ out) {
    __shared__ float ssc[D], ssh[D];
    if (threadIdx.x < D) {
        int c = threadIdx.x;
        float m  = g_colsum[c] * (1.0f / N_NODES);
        float va = g_colsq[c] * (1.0f / N_NODES) - m * m;
        float rs = rsqrtf(va + BN_EPS);
        float sc = rs * gamma[c];
        ssc[c] = sc;
        ssh[c] = beta[c] - m * sc;
    }
    __syncthreads();
    int i = blockIdx.x * blockDim.x + threadIdx.x;
    if (i < N_NODES) g_cnt[i] = 0;     // invariant: cnt zeroed for next run
    if (i >= N_NODES * (D / 4)) return;
    int c4 = i & (D / 4 - 1);
    float4 y  = ((const float4*)g_y)[i];
    float4 hh = ((const float4*)h)[i];
    float4 o;
    o.x = hh.x + y.x * ssc[c4 * 4 + 0] + ssh[c4 * 4 + 0];
    o.y = hh.y + y.y * ssc[c4 * 4 + 1] + ssh[c4 * 4 + 1];
    o.z = hh.z + y.z * ssc[c4 * 4 + 2] + ssh[c4 * 4 + 2];
    o.w = hh.w + y.w * ssc[c4 * 4 + 3] + ssh[c4 * 4 + 3];
    ((float4*)out)[i] = o;
}

// ---------------- launch ----------------
extern "C" void kernel_launch(void* const* d_in, const int* in_sizes, int n_in,
                              void* d_out, int out_size) {
    const float* h      = (const float*)d_in[0];
    const float* snorm  = (const float*)d_in[1];
    const float* Ws     = (const float*)d_in[2];
    const float* Wn     = (const float*)d_in[3];
    const float* bias   = (const float*)d_in[4];
    const float* gamma  = (const float*)d_in[5];
    const float* beta   = (const float*)d_in[6];
    const int*   src    = (const int*)d_in[7];
    const int*   dst    = (const int*)d_in[8];
    float* out = (float*)d_out;

    cudaFuncSetAttribute(k_gemm_mma, cudaFuncAttributeMaxDynamicSharedMemorySize,
                         SM_TOTAL);

    int nd4_blocks = (N_NODES * (D / 4) + 255) / 256;   // 5000
    int edge_blocks = (N_EDGES + 255) / 256;            // 2500
    int gemm_blocks = N_NODES / 64;                     // 625
    int node_blocks = (N_NODES + 255) / 256;            // 157

    k_prep<<<nd4_blocks, 256>>>(h, dst, Ws, Wn);
    k_scan<<<node_blocks, 256>>>();
    k_fill<<<edge_blocks, 256>>>(src, dst);
    k_gather<<<(N_NODES * 32 + 255) / 256, 256>>>();
    k_gemm_mma<<<gemm_blocks, 256, SM_TOTAL>>>(h, bias, snorm);
    k_final<<<nd4_blocks, 256>>>(h, gamma, beta, out);
}